// round 7
// baseline (speedup 1.0000x reference)
#include <cuda_runtime.h>
#include <math.h>

// ---------------------------------------------------------------------------
// Scratch (static __device__ arrays; no dynamic allocation allowed)
// ---------------------------------------------------------------------------
#define MAX_N 50048

__device__ __align__(16) float g_segsum[MAX_N];
__device__ __align__(16) float g_cnt[MAX_N];
__device__ __align__(16) float g_agg[50000 * 64];

typedef unsigned long long u64;

// packed fp32x2 FMA (FFMA2) — ptxas never emits this from C++; PTX-only.
#define FMA2(d, a, b) asm("fma.rn.f32x2 %0, %1, %2, %0;" : "+l"(d) : "l"(a), "l"(b))

union F4U2 { float4 f; u64 u[2]; };
union U2F  { u64 u; float2 f; };

__device__ __forceinline__ float lane_of(u64 v, int h) {
    U2F t; t.u = v; return h ? t.f.y : t.f.x;
}

__device__ __forceinline__ void red_add_v4(float* p, float4 v) {
    asm volatile("red.global.add.v4.f32 [%0], {%1,%2,%3,%4};"
                 :: "l"(__cvta_generic_to_global(p)),
                    "f"(v.x), "f"(v.y), "f"(v.z), "f"(v.w)
                 : "memory");
}

// ---------------------------------------------------------------------------
// K0: zero-init scratch
// ---------------------------------------------------------------------------
__global__ void k0_init(int N) {
    int i = blockIdx.x * blockDim.x + threadIdx.x;
    if (i < N) {
        g_segsum[i] = 0.0f;
        g_cnt[i]    = 0.0f;
    }
    if (i < N * 64) g_agg[i] = 0.0f;
}

// ---------------------------------------------------------------------------
// K1: fused edge kernel, 512 threads, M-packed FFMA2, zero in-loop DUPs.
//   Thread tile: 4 rows (2 packed pairs) x 4 cols.
//   Weights staged DUPLICATED in smem so b-pairs load directly as u64.
// Shared (floats):
//   sX    [192][128]  24576   (X tile, K-major transposed)
//   sWd   [32][128]    4096   (W1 k-slab, duplicated cols)
//   sH    [64][132]    8448   (hidden chunk, transposed)
//   sWe2d [128][128]  16384   (We2, duplicated cols)
//   sLog  [128]         128
// total 53632 floats = 214528 B  (1 CTA/SM)
// ---------------------------------------------------------------------------
#define EDGE_SMEM_FLOATS (24576 + 4096 + 8448 + 16384 + 128)
#define EDGE_SMEM_BYTES  (EDGE_SMEM_FLOATS * 4)

__global__ __launch_bounds__(512, 1)
void k1_edge(const float* __restrict__ nf,  const float* __restrict__ ef,
             const float* __restrict__ We1, const float* __restrict__ be1,
             const float* __restrict__ We2, const float* __restrict__ be2,
             const float* __restrict__ Wa1, const float* __restrict__ ba1,
             const float* __restrict__ Wa2, const float* __restrict__ ba2,
             const int* __restrict__ src,   const int* __restrict__ dst,
             float* __restrict__ uef_out, int E)
{
    extern __shared__ float sm[];
    float* sX    = sm;                 // [192][128]
    float* sWd   = sX + 24576;         // [32][128] duplicated
    float* sH    = sWd + 4096;         // [64][132]
    float* sWe2d = sH + 8448;          // [128][128] duplicated
    float* sLog  = sWe2d + 16384;      // [128]

    const int tid = threadIdx.x;
    const int tx  = tid & 15;          // col quad (4 cols)
    const int ty  = tid >> 4;          // 0..31, rows ty*4..ty*4+3
    const int e0  = blockIdx.x * 128;

    // stage We2 duplicated: src [128][64] -> dst [128][128] {w,w} pairs
    #pragma unroll
    for (int i = tid; i < 2048; i += 512) {
        float4 w = ((const float4*)We2)[i];
        *(float4*)&sWe2d[i * 8 + 0] = make_float4(w.x, w.x, w.y, w.y);
        *(float4*)&sWe2d[i * 8 + 4] = make_float4(w.z, w.z, w.w, w.w);
    }
    if (tid < 128) sLog[tid] = 0.0f;

    // gather X tile, transposed into sX[k][m]
    #pragma unroll 4
    for (int it = 0; it < 12; ++it) {
        int task = it * 512 + tid;
        int m = task & 127;
        int s = task >> 7;             // 0..47 (float4 segment)
        int e = e0 + m;
        float4 v = make_float4(0.f, 0.f, 0.f, 0.f);
        if (e < E) {
            if (s < 16)      v = *(const float4*)&ef[(size_t)e * 64 + s * 4];
            else if (s < 32) { int r = src[e]; v = *(const float4*)&nf[(size_t)r * 64 + (s - 16) * 4]; }
            else             { int r = dst[e]; v = *(const float4*)&nf[(size_t)r * 64 + (s - 32) * 4]; }
        }
        int k0 = s * 4;
        sX[(k0 + 0) * 128 + m] = v.x;
        sX[(k0 + 1) * 128 + m] = v.y;
        sX[(k0 + 2) * 128 + m] = v.z;
        sX[(k0 + 3) * 128 + m] = v.w;
    }
    __syncthreads();

    // uef accumulators: 2 row-pairs x 4 cols, packed over M
    u64 uacc2[2][4];
    #pragma unroll
    for (int p = 0; p < 2; ++p)
        #pragma unroll
        for (int j = 0; j < 4; ++j) uacc2[p][j] = 0ull;

    #pragma unroll 1
    for (int chunk = 0; chunk < 4; ++chunk) {
        const float* W1 = (chunk < 2) ? We1 : Wa1;
        const float* b1 = (chunk < 2) ? be1 : ba1;
        const int c0 = (chunk & 1) * 64;

        u64 acc2[2][4];
        #pragma unroll
        for (int p = 0; p < 2; ++p)
            #pragma unroll
            for (int j = 0; j < 4; ++j) acc2[p][j] = 0ull;

        #pragma unroll 1
        for (int kc = 0; kc < 6; ++kc) {
            __syncthreads();
            // stage 32x64 W1 slab duplicated -> sWd[32][128]
            {
                int row = tid >> 4;            // 0..31
                int cq  = tid & 15;            // 0..15
                float4 w = *(const float4*)&W1[(size_t)(kc * 32 + row) * 128 + c0 + cq * 4];
                *(float4*)&sWd[row * 128 + cq * 8 + 0] = make_float4(w.x, w.x, w.y, w.y);
                *(float4*)&sWd[row * 128 + cq * 8 + 4] = make_float4(w.z, w.z, w.w, w.w);
            }
            __syncthreads();
            #pragma unroll
            for (int kk = 0; kk < 32; ++kk) {
                F4U2 A;  A.f  = *(const float4*)&sX[(kc * 32 + kk) * 128 + ty * 4];
                F4U2 B0; B0.f = *(const float4*)&sWd[kk * 128 + tx * 8];
                F4U2 B1; B1.f = *(const float4*)&sWd[kk * 128 + tx * 8 + 4];
                FMA2(acc2[0][0], A.u[0], B0.u[0]);
                FMA2(acc2[0][1], A.u[0], B0.u[1]);
                FMA2(acc2[0][2], A.u[0], B1.u[0]);
                FMA2(acc2[0][3], A.u[0], B1.u[1]);
                FMA2(acc2[1][0], A.u[1], B0.u[0]);
                FMA2(acc2[1][1], A.u[1], B0.u[1]);
                FMA2(acc2[1][2], A.u[1], B1.u[0]);
                FMA2(acc2[1][3], A.u[1], B1.u[1]);
            }
        }

        // unpack + bias + ReLU  (acc[i][j]: row ty*4+i, col c0+tx*4+j)
        float acc[4][4];
        #pragma unroll
        for (int i = 0; i < 4; ++i)
            #pragma unroll
            for (int j = 0; j < 4; ++j)
                acc[i][j] = lane_of(acc2[i >> 1][j], i & 1);

        float bj0 = b1[c0 + tx * 4 + 0], bj1 = b1[c0 + tx * 4 + 1];
        float bj2 = b1[c0 + tx * 4 + 2], bj3 = b1[c0 + tx * 4 + 3];
        #pragma unroll
        for (int i = 0; i < 4; ++i) {
            acc[i][0] = fmaxf(acc[i][0] + bj0, 0.0f);
            acc[i][1] = fmaxf(acc[i][1] + bj1, 0.0f);
            acc[i][2] = fmaxf(acc[i][2] + bj2, 0.0f);
            acc[i][3] = fmaxf(acc[i][3] + bj3, 0.0f);
        }

        if (chunk < 2) {
            // store H chunk transposed: sH[c][m], c = tx*4+j, m = ty*4..+3
            #pragma unroll
            for (int j = 0; j < 4; ++j)
                *(float4*)&sH[(tx * 4 + j) * 132 + ty * 4] =
                    make_float4(acc[0][j], acc[1][j], acc[2][j], acc[3][j]);
            __syncthreads();
            // GEMM2 partial: uef += H_chunk @ We2[chunk*64 .. +64]
            #pragma unroll
            for (int hh = 0; hh < 64; ++hh) {
                F4U2 A;  A.f  = *(const float4*)&sH[hh * 132 + ty * 4];
                F4U2 B0; B0.f = *(const float4*)&sWe2d[(chunk * 64 + hh) * 128 + tx * 8];
                F4U2 B1; B1.f = *(const float4*)&sWe2d[(chunk * 64 + hh) * 128 + tx * 8 + 4];
                FMA2(uacc2[0][0], A.u[0], B0.u[0]);
                FMA2(uacc2[0][1], A.u[0], B0.u[1]);
                FMA2(uacc2[0][2], A.u[0], B1.u[0]);
                FMA2(uacc2[0][3], A.u[0], B1.u[1]);
                FMA2(uacc2[1][0], A.u[1], B0.u[0]);
                FMA2(uacc2[1][1], A.u[1], B0.u[1]);
                FMA2(uacc2[1][2], A.u[1], B1.u[0]);
                FMA2(uacc2[1][3], A.u[1], B1.u[1]);
            }
            __syncthreads();   // protect sH before next chunk rewrites it
        } else {
            float w0 = Wa2[(chunk - 2) * 64 + tx * 4 + 0];
            float w1 = Wa2[(chunk - 2) * 64 + tx * 4 + 1];
            float w2 = Wa2[(chunk - 2) * 64 + tx * 4 + 2];
            float w3 = Wa2[(chunk - 2) * 64 + tx * 4 + 3];
            #pragma unroll
            for (int i = 0; i < 4; ++i) {
                float p = acc[i][0] * w0 + acc[i][1] * w1 + acc[i][2] * w2 + acc[i][3] * w3;
                p += __shfl_xor_sync(0xFFFFFFFFu, p, 1);
                p += __shfl_xor_sync(0xFFFFFFFFu, p, 2);
                p += __shfl_xor_sync(0xFFFFFFFFu, p, 4);
                p += __shfl_xor_sync(0xFFFFFFFFu, p, 8);
                if (tx == 0) sLog[ty * 4 + i] += p;
            }
        }
    }
    __syncthreads();

    // ---- epilogue: exp(logit), segsum/cnt atomics (reuse sWd as sExp/sDst) --
    float* sExpF = sWd;               // [128]
    int*   sDstI = (int*)(sWd + 128); // [128]
    if (tid < 128) {
        int e = e0 + tid;
        if (e < E) {
            float lg = sLog[tid] + ba2[0];
            float ex = __expf(lg);    // no max-subtraction: logits are O(1)
            sExpF[tid] = ex;
            int d = dst[e];
            sDstI[tid] = d;
            atomicAdd(&g_segsum[d], ex);
            atomicAdd(&g_cnt[d], 1.0f);
        }
    }
    __syncthreads();

    // uef write (+be2) and unnormalized attention-weighted aggregate
    float o0 = be2[tx * 4 + 0], o1 = be2[tx * 4 + 1];
    float o2 = be2[tx * 4 + 2], o3 = be2[tx * 4 + 3];
    #pragma unroll
    for (int i = 0; i < 4; ++i) {
        int m = ty * 4 + i;
        int e = e0 + m;
        if (e < E) {
            int p = i >> 1, h = i & 1;
            float4 o = make_float4(lane_of(uacc2[p][0], h) + o0,
                                   lane_of(uacc2[p][1], h) + o1,
                                   lane_of(uacc2[p][2], h) + o2,
                                   lane_of(uacc2[p][3], h) + o3);
            *(float4*)&uef_out[(size_t)e * 64 + tx * 4] = o;
            float ex = sExpF[m];
            int   d  = sDstI[m];
            float4 v = make_float4(o.x * ex, o.y * ex, o.z * ex, o.w * ex);
            red_add_v4(&g_agg[(size_t)d * 64 + tx * 4], v);
        }
    }
}

// ---------------------------------------------------------------------------
// K3: node MLP, 512 threads, same M-packed FFMA2 scheme.
// Shared: sX[128][128] 16384, sWd[32][128] 4096, sH[64][132] 8448,
//         sWn2d[128][128] 16384, sRs[128] 128  -> 45440 floats = 181760 B
// ---------------------------------------------------------------------------
#define NODE_SMEM_FLOATS (16384 + 4096 + 8448 + 16384 + 128)
#define NODE_SMEM_BYTES  (NODE_SMEM_FLOATS * 4)

__global__ __launch_bounds__(512, 1)
void k3_node(const float* __restrict__ nf,
             const float* __restrict__ Wn1, const float* __restrict__ bn1,
             const float* __restrict__ Wn2, const float* __restrict__ bn2,
             float* __restrict__ unf_out, int N)
{
    extern __shared__ float sm[];
    float* sX    = sm;             // [128][128]
    float* sWd   = sX + 16384;     // [32][128] duplicated
    float* sH    = sWd + 4096;     // [64][132]
    float* sWn2d = sH + 8448;      // [128][128] duplicated
    float* sRs   = sWn2d + 16384;  // [128]

    const int tid = threadIdx.x;
    const int tx  = tid & 15;
    const int ty  = tid >> 4;
    const int n0  = blockIdx.x * 128;

    #pragma unroll
    for (int i = tid; i < 2048; i += 512) {
        float4 w = ((const float4*)Wn2)[i];
        *(float4*)&sWn2d[i * 8 + 0] = make_float4(w.x, w.x, w.y, w.y);
        *(float4*)&sWn2d[i * 8 + 4] = make_float4(w.z, w.z, w.w, w.w);
    }
    if (tid < 128) {
        int n = n0 + tid;
        float rs = 0.0f;
        if (n < N) {
            float c = g_cnt[n];
            if (c > 0.5f) rs = 1.0f / (g_segsum[n] * c);
        }
        sRs[tid] = rs;
    }
    __syncthreads();

    // gather X2 = [agg*rs | nf] transposed
    #pragma unroll 4
    for (int it = 0; it < 8; ++it) {
        int task = it * 512 + tid;
        int m = task & 127;
        int s = task >> 7;    // 0..31
        int n = n0 + m;
        float4 v = make_float4(0.f, 0.f, 0.f, 0.f);
        if (n < N) {
            if (s < 16) {
                v = *(const float4*)&g_agg[(size_t)n * 64 + s * 4];
                float rs = sRs[m];
                v.x *= rs; v.y *= rs; v.z *= rs; v.w *= rs;
            } else {
                v = *(const float4*)&nf[(size_t)n * 64 + (s - 16) * 4];
            }
        }
        int k0 = s * 4;
        sX[(k0 + 0) * 128 + m] = v.x;
        sX[(k0 + 1) * 128 + m] = v.y;
        sX[(k0 + 2) * 128 + m] = v.z;
        sX[(k0 + 3) * 128 + m] = v.w;
    }
    __syncthreads();

    u64 uacc2[2][4];
    #pragma unroll
    for (int p = 0; p < 2; ++p)
        #pragma unroll
        for (int j = 0; j < 4; ++j) uacc2[p][j] = 0ull;

    #pragma unroll 1
    for (int chunk = 0; chunk < 2; ++chunk) {
        const int c0 = chunk * 64;
        u64 acc2[2][4];
        #pragma unroll
        for (int p = 0; p < 2; ++p)
            #pragma unroll
            for (int j = 0; j < 4; ++j) acc2[p][j] = 0ull;

        #pragma unroll 1
        for (int kc = 0; kc < 4; ++kc) {
            __syncthreads();
            {
                int row = tid >> 4;
                int cq  = tid & 15;
                float4 w = *(const float4*)&Wn1[(size_t)(kc * 32 + row) * 128 + c0 + cq * 4];
                *(float4*)&sWd[row * 128 + cq * 8 + 0] = make_float4(w.x, w.x, w.y, w.y);
                *(float4*)&sWd[row * 128 + cq * 8 + 4] = make_float4(w.z, w.z, w.w, w.w);
            }
            __syncthreads();
            #pragma unroll
            for (int kk = 0; kk < 32; ++kk) {
                F4U2 A;  A.f  = *(const float4*)&sX[(kc * 32 + kk) * 128 + ty * 4];
                F4U2 B0; B0.f = *(const float4*)&sWd[kk * 128 + tx * 8];
                F4U2 B1; B1.f = *(const float4*)&sWd[kk * 128 + tx * 8 + 4];
                FMA2(acc2[0][0], A.u[0], B0.u[0]);
                FMA2(acc2[0][1], A.u[0], B0.u[1]);
                FMA2(acc2[0][2], A.u[0], B1.u[0]);
                FMA2(acc2[0][3], A.u[0], B1.u[1]);
                FMA2(acc2[1][0], A.u[1], B0.u[0]);
                FMA2(acc2[1][1], A.u[1], B0.u[1]);
                FMA2(acc2[1][2], A.u[1], B1.u[0]);
                FMA2(acc2[1][3], A.u[1], B1.u[1]);
            }
        }

        float acc[4][4];
        #pragma unroll
        for (int i = 0; i < 4; ++i)
            #pragma unroll
            for (int j = 0; j < 4; ++j)
                acc[i][j] = lane_of(acc2[i >> 1][j], i & 1);

        float bj0 = bn1[c0 + tx * 4 + 0], bj1 = bn1[c0 + tx * 4 + 1];
        float bj2 = bn1[c0 + tx * 4 + 2], bj3 = bn1[c0 + tx * 4 + 3];
        #pragma unroll
        for (int i = 0; i < 4; ++i) {
            acc[i][0] = fmaxf(acc[i][0] + bj0, 0.0f);
            acc[i][1] = fmaxf(acc[i][1] + bj1, 0.0f);
            acc[i][2] = fmaxf(acc[i][2] + bj2, 0.0f);
            acc[i][3] = fmaxf(acc[i][3] + bj3, 0.0f);
        }

        #pragma unroll
        for (int j = 0; j < 4; ++j)
            *(float4*)&sH[(tx * 4 + j) * 132 + ty * 4] =
                make_float4(acc[0][j], acc[1][j], acc[2][j], acc[3][j]);
        __syncthreads();
        #pragma unroll
        for (int hh = 0; hh < 64; ++hh) {
            F4U2 A;  A.f  = *(const float4*)&sH[hh * 132 + ty * 4];
            F4U2 B0; B0.f = *(const float4*)&sWn2d[(c0 + hh) * 128 + tx * 8];
            F4U2 B1; B1.f = *(const float4*)&sWn2d[(c0 + hh) * 128 + tx * 8 + 4];
            FMA2(uacc2[0][0], A.u[0], B0.u[0]);
            FMA2(uacc2[0][1], A.u[0], B0.u[1]);
            FMA2(uacc2[0][2], A.u[0], B1.u[0]);
            FMA2(uacc2[0][3], A.u[0], B1.u[1]);
            FMA2(uacc2[1][0], A.u[1], B0.u[0]);
            FMA2(uacc2[1][1], A.u[1], B0.u[1]);
            FMA2(uacc2[1][2], A.u[1], B1.u[0]);
            FMA2(uacc2[1][3], A.u[1], B1.u[1]);
        }
        __syncthreads();
    }

    float o0 = bn2[tx * 4 + 0], o1 = bn2[tx * 4 + 1];
    float o2 = bn2[tx * 4 + 2], o3 = bn2[tx * 4 + 3];
    #pragma unroll
    for (int i = 0; i < 4; ++i) {
        int n = n0 + ty * 4 + i;
        if (n < N) {
            int p = i >> 1, h = i & 1;
            float4 o = make_float4(lane_of(uacc2[p][0], h) + o0,
                                   lane_of(uacc2[p][1], h) + o1,
                                   lane_of(uacc2[p][2], h) + o2,
                                   lane_of(uacc2[p][3], h) + o3);
            *(float4*)&unf_out[(size_t)n * 64 + tx * 4] = o;
        }
    }
}

// ---------------------------------------------------------------------------
// launch
// ---------------------------------------------------------------------------
extern "C" void kernel_launch(void* const* d_in, const int* in_sizes, int n_in,
                              void* d_out, int out_size)
{
    const float* nf  = (const float*)d_in[0];
    const float* ef  = (const float*)d_in[1];
    const float* We1 = (const float*)d_in[2];
    const float* be1 = (const float*)d_in[3];
    const float* We2 = (const float*)d_in[4];
    const float* be2 = (const float*)d_in[5];
    const float* Wa1 = (const float*)d_in[6];
    const float* ba1 = (const float*)d_in[7];
    const float* Wa2 = (const float*)d_in[8];
    const float* ba2 = (const float*)d_in[9];
    const float* Wn1 = (const float*)d_in[10];
    const float* bn1 = (const float*)d_in[11];
    const float* Wn2 = (const float*)d_in[12];
    const float* bn2 = (const float*)d_in[13];
    const int*   src = (const int*)d_in[14];
    const int*   dst = (const int*)d_in[15];

    const int N = in_sizes[0] / 64;
    const int E = in_sizes[14];

    float* unf_out = (float*)d_out;                       // [N,64] first (ref return order)
    float* uef_out = (float*)d_out + (size_t)N * 64;      // [E,64] second

    cudaFuncSetAttribute(k1_edge, cudaFuncAttributeMaxDynamicSharedMemorySize, EDGE_SMEM_BYTES);
    cudaFuncSetAttribute(k3_node, cudaFuncAttributeMaxDynamicSharedMemorySize, NODE_SMEM_BYTES);

    k0_init<<<(N * 64 + 255) / 256, 256>>>(N);
    k1_edge<<<(E + 127) / 128, 512, EDGE_SMEM_BYTES>>>(
        nf, ef, We1, be1, We2, be2, Wa1, ba1, Wa2, ba2, src, dst, uef_out, E);
    k3_node<<<(N + 127) / 128, 512, NODE_SMEM_BYTES>>>(
        nf, Wn1, bn1, Wn2, bn2, unf_out, N);
}

// round 8
// speedup vs baseline: 1.8100x; 1.8100x over previous
#include <cuda_runtime.h>
#include <math.h>

// ---------------------------------------------------------------------------
// Scratch (static __device__ arrays; no dynamic allocation allowed)
// ---------------------------------------------------------------------------
#define MAX_N 50048

__device__ __align__(16) float g_segsum[MAX_N];
__device__ __align__(16) float g_cnt[MAX_N];
__device__ __align__(16) float g_agg[50000 * 64];

typedef unsigned long long u64;

// packed fp32x2 FMA (FFMA2) — ptxas never emits this from C++; PTX-only.
#define FMA2(d, a, b) asm("fma.rn.f32x2 %0, %1, %2, %0;" : "+l"(d) : "l"(a), "l"(b))
// split / build a packed pair (epilogue only)
#define UNPK(lo, hi, v) asm("mov.b64 {%0,%1}, %2;" : "=f"(lo), "=f"(hi) : "l"(v))
#define PACK(d, lo, hi) asm("mov.b64 %0, {%1,%2};" : "=l"(d) : "f"(lo), "f"(hi))

__device__ __forceinline__ void red_add_v4(float* p, float4 v) {
    asm volatile("red.global.add.v4.f32 [%0], {%1,%2,%3,%4};"
                 :: "l"(__cvta_generic_to_global(p)),
                    "f"(v.x), "f"(v.y), "f"(v.z), "f"(v.w)
                 : "memory");
}

// ---------------------------------------------------------------------------
// K0: zero-init scratch
// ---------------------------------------------------------------------------
__global__ void k0_init(int N) {
    int i = blockIdx.x * blockDim.x + threadIdx.x;
    if (i < N) {
        g_segsum[i] = 0.0f;
        g_cnt[i]    = 0.0f;
    }
    if (i < N * 64) g_agg[i] = 0.0f;
}

// ---------------------------------------------------------------------------
// K1: fused edge kernel, 512 threads, M-packed FFMA2.
//   Lane map: rg = (tid&15)|((tid&256)>>4)  -> rows rg*4..+3 (low lane bits)
//             cg = (tid>>4)&15              -> cols cg*4..+3 (high bits)
//   => A (activations) is the 256B/warp contiguous LDS operand,
//      B (duplicated weights) is a 2-address broadcast per warp.
//   Hot loops: ulonglong2 loads only, no unions, no per-iter MOVs.
// Shared (floats): sX[192][128] 24576, sWd[32][128] 4096 (dup),
//                  sH[64][132] 8448, sWe2d[128][128] 16384 (dup), sLog[128]
// total 53632 floats = 214528 B (1 CTA/SM)
// ---------------------------------------------------------------------------
#define EDGE_SMEM_FLOATS (24576 + 4096 + 8448 + 16384 + 128)
#define EDGE_SMEM_BYTES  (EDGE_SMEM_FLOATS * 4)

__global__ __launch_bounds__(512, 1)
void k1_edge(const float* __restrict__ nf,  const float* __restrict__ ef,
             const float* __restrict__ We1, const float* __restrict__ be1,
             const float* __restrict__ We2, const float* __restrict__ be2,
             const float* __restrict__ Wa1, const float* __restrict__ ba1,
             const float* __restrict__ Wa2, const float* __restrict__ ba2,
             const int* __restrict__ src,   const int* __restrict__ dst,
             float* __restrict__ uef_out, int E)
{
    extern __shared__ float sm[];
    float* sX    = sm;                 // [192][128]
    float* sWd   = sX + 24576;         // [32][128] duplicated
    float* sH    = sWd + 4096;         // [64][132]
    float* sWe2d = sH + 8448;          // [128][128] duplicated
    float* sLog  = sWe2d + 16384;      // [128]

    const int tid = threadIdx.x;
    const int rg  = (tid & 15) | ((tid & 256) >> 4);   // 0..31
    const int cg  = (tid >> 4) & 15;                   // 0..15
    const int e0  = blockIdx.x * 128;

    // stage We2 duplicated: [128][64] -> [128][128] {w,w} pairs
    for (int i = tid; i < 2048; i += 512) {
        float4 w = ((const float4*)We2)[i];
        *(float4*)&sWe2d[i * 8 + 0] = make_float4(w.x, w.x, w.y, w.y);
        *(float4*)&sWe2d[i * 8 + 4] = make_float4(w.z, w.z, w.w, w.w);
    }
    if (tid < 128) sLog[tid] = 0.0f;

    // gather X tile, transposed into sX[k][m]
    for (int it = 0; it < 12; ++it) {
        int task = it * 512 + tid;
        int m = task & 127;
        int s = task >> 7;             // 0..47 (float4 segment)
        int e = e0 + m;
        float4 v = make_float4(0.f, 0.f, 0.f, 0.f);
        if (e < E) {
            if (s < 16)      v = *(const float4*)&ef[(size_t)e * 64 + s * 4];
            else if (s < 32) { int r = src[e]; v = *(const float4*)&nf[(size_t)r * 64 + (s - 16) * 4]; }
            else             { int r = dst[e]; v = *(const float4*)&nf[(size_t)r * 64 + (s - 32) * 4]; }
        }
        int k0 = s * 4;
        sX[(k0 + 0) * 128 + m] = v.x;
        sX[(k0 + 1) * 128 + m] = v.y;
        sX[(k0 + 2) * 128 + m] = v.z;
        sX[(k0 + 3) * 128 + m] = v.w;
    }
    __syncthreads();

    u64 uacc[2][4];
    #pragma unroll
    for (int p = 0; p < 2; ++p)
        #pragma unroll
        for (int j = 0; j < 4; ++j) uacc[p][j] = 0ull;

    #pragma unroll 1
    for (int chunk = 0; chunk < 4; ++chunk) {
        const float* W1  = (chunk < 2) ? We1 : Wa1;
        const float* b1v = (chunk < 2) ? be1 : ba1;
        const int c0 = (chunk & 1) * 64;

        u64 acc[2][4];
        #pragma unroll
        for (int p = 0; p < 2; ++p)
            #pragma unroll
            for (int j = 0; j < 4; ++j) acc[p][j] = 0ull;

        #pragma unroll 1
        for (int kc = 0; kc < 6; ++kc) {
            __syncthreads();
            {   // stage 32x64 W1 slab duplicated -> sWd[32][128]
                int row = tid >> 4;            // 0..31
                int cq  = tid & 15;            // 0..15
                float4 w = *(const float4*)&W1[(size_t)(kc * 32 + row) * 128 + c0 + cq * 4];
                *(float4*)&sWd[row * 128 + cq * 8 + 0] = make_float4(w.x, w.x, w.y, w.y);
                *(float4*)&sWd[row * 128 + cq * 8 + 4] = make_float4(w.z, w.z, w.w, w.w);
            }
            __syncthreads();
            const float* xb = &sX[(kc * 32) * 128 + rg * 4];
            const float* wb = &sWd[cg * 8];
            #pragma unroll
            for (int kk = 0; kk < 32; ++kk) {
                ulonglong2 A  = *(const ulonglong2*)(xb + kk * 128);
                ulonglong2 B0 = *(const ulonglong2*)(wb + kk * 128);
                ulonglong2 B1 = *(const ulonglong2*)(wb + kk * 128 + 4);
                FMA2(acc[0][0], A.x, B0.x);
                FMA2(acc[0][1], A.x, B0.y);
                FMA2(acc[0][2], A.x, B1.x);
                FMA2(acc[0][3], A.x, B1.y);
                FMA2(acc[1][0], A.y, B0.x);
                FMA2(acc[1][1], A.y, B0.y);
                FMA2(acc[1][2], A.y, B1.x);
                FMA2(acc[1][3], A.y, B1.y);
            }
        }

        // unpack + bias + ReLU   (a[i][j]: row rg*4+i, col c0+cg*4+j)
        float a[4][4];
        #pragma unroll
        for (int p = 0; p < 2; ++p)
            #pragma unroll
            for (int j = 0; j < 4; ++j)
                UNPK(a[2 * p][j], a[2 * p + 1][j], acc[p][j]);

        float bb0 = b1v[c0 + cg * 4 + 0], bb1 = b1v[c0 + cg * 4 + 1];
        float bb2 = b1v[c0 + cg * 4 + 2], bb3 = b1v[c0 + cg * 4 + 3];
        #pragma unroll
        for (int i = 0; i < 4; ++i) {
            a[i][0] = fmaxf(a[i][0] + bb0, 0.0f);
            a[i][1] = fmaxf(a[i][1] + bb1, 0.0f);
            a[i][2] = fmaxf(a[i][2] + bb2, 0.0f);
            a[i][3] = fmaxf(a[i][3] + bb3, 0.0f);
        }

        if (chunk < 2) {
            // pack and store H transposed: sH[c][m], packed pairs along m
            #pragma unroll
            for (int j = 0; j < 4; ++j) {
                u64 v0, v1;
                PACK(v0, a[0][j], a[1][j]);
                PACK(v1, a[2][j], a[3][j]);
                *(u64*)&sH[(cg * 4 + j) * 132 + rg * 4]     = v0;
                *(u64*)&sH[(cg * 4 + j) * 132 + rg * 4 + 2] = v1;
            }
            __syncthreads();
            const float* hb  = &sH[rg * 4];
            const float* w2b = &sWe2d[(chunk * 64) * 128 + cg * 8];
            #pragma unroll
            for (int hh = 0; hh < 64; ++hh) {
                ulonglong2 A  = *(const ulonglong2*)(hb + hh * 132);
                ulonglong2 B0 = *(const ulonglong2*)(w2b + hh * 128);
                ulonglong2 B1 = *(const ulonglong2*)(w2b + hh * 128 + 4);
                FMA2(uacc[0][0], A.x, B0.x);
                FMA2(uacc[0][1], A.x, B0.y);
                FMA2(uacc[0][2], A.x, B1.x);
                FMA2(uacc[0][3], A.x, B1.y);
                FMA2(uacc[1][0], A.y, B0.x);
                FMA2(uacc[1][1], A.y, B0.y);
                FMA2(uacc[1][2], A.y, B1.x);
                FMA2(uacc[1][3], A.y, B1.y);
            }
            __syncthreads();   // protect sH before next chunk rewrites it
        } else {
            float w0 = Wa2[(chunk - 2) * 64 + cg * 4 + 0];
            float w1 = Wa2[(chunk - 2) * 64 + cg * 4 + 1];
            float w2 = Wa2[(chunk - 2) * 64 + cg * 4 + 2];
            float w3 = Wa2[(chunk - 2) * 64 + cg * 4 + 3];
            #pragma unroll
            for (int i = 0; i < 4; ++i) {
                float p = a[i][0] * w0 + a[i][1] * w1 + a[i][2] * w2 + a[i][3] * w3;
                atomicAdd(&sLog[rg * 4 + i], p);   // cols span warps -> smem reduce
            }
        }
    }
    __syncthreads();

    // ---- epilogue: exp(logit), segsum/cnt atomics (reuse sWd as sExp/sDst) --
    float* sExpF = sWd;               // [128]
    int*   sDstI = (int*)(sWd + 128); // [128]
    if (tid < 128) {
        int e = e0 + tid;
        if (e < E) {
            float lg = sLog[tid] + ba2[0];
            float ex = __expf(lg);    // no max-subtraction: logits are O(1)
            sExpF[tid] = ex;
            int d = dst[e];
            sDstI[tid] = d;
            atomicAdd(&g_segsum[d], ex);
            atomicAdd(&g_cnt[d], 1.0f);
        }
    }
    __syncthreads();

    // uef write (+be2) and unnormalized attention-weighted aggregate
    float u[4][4];
    #pragma unroll
    for (int p = 0; p < 2; ++p)
        #pragma unroll
        for (int j = 0; j < 4; ++j)
            UNPK(u[2 * p][j], u[2 * p + 1][j], uacc[p][j]);

    float o0 = be2[cg * 4 + 0], o1 = be2[cg * 4 + 1];
    float o2 = be2[cg * 4 + 2], o3 = be2[cg * 4 + 3];
    #pragma unroll
    for (int i = 0; i < 4; ++i) {
        int m = rg * 4 + i;
        int e = e0 + m;
        if (e < E) {
            float4 o = make_float4(u[i][0] + o0, u[i][1] + o1,
                                   u[i][2] + o2, u[i][3] + o3);
            *(float4*)&uef_out[(size_t)e * 64 + cg * 4] = o;
            float ex = sExpF[m];
            int   d  = sDstI[m];
            float4 v = make_float4(o.x * ex, o.y * ex, o.z * ex, o.w * ex);
            red_add_v4(&g_agg[(size_t)d * 64 + cg * 4], v);
        }
    }
}

// ---------------------------------------------------------------------------
// K3: node MLP, 512 threads, same scheme.
// Shared: sX[128][128] 16384, sWd[32][128] 4096, sH[64][132] 8448,
//         sWn2d[128][128] 16384, sRs[128]  -> 45440 floats = 181760 B
// ---------------------------------------------------------------------------
#define NODE_SMEM_FLOATS (16384 + 4096 + 8448 + 16384 + 128)
#define NODE_SMEM_BYTES  (NODE_SMEM_FLOATS * 4)

__global__ __launch_bounds__(512, 1)
void k3_node(const float* __restrict__ nf,
             const float* __restrict__ Wn1, const float* __restrict__ bn1,
             const float* __restrict__ Wn2, const float* __restrict__ bn2,
             float* __restrict__ unf_out, int N)
{
    extern __shared__ float sm[];
    float* sX    = sm;             // [128][128]
    float* sWd   = sX + 16384;     // [32][128] duplicated
    float* sH    = sWd + 4096;     // [64][132]
    float* sWn2d = sH + 8448;      // [128][128] duplicated
    float* sRs   = sWn2d + 16384;  // [128]

    const int tid = threadIdx.x;
    const int rg  = (tid & 15) | ((tid & 256) >> 4);
    const int cg  = (tid >> 4) & 15;
    const int n0  = blockIdx.x * 128;

    for (int i = tid; i < 2048; i += 512) {
        float4 w = ((const float4*)Wn2)[i];
        *(float4*)&sWn2d[i * 8 + 0] = make_float4(w.x, w.x, w.y, w.y);
        *(float4*)&sWn2d[i * 8 + 4] = make_float4(w.z, w.z, w.w, w.w);
    }
    if (tid < 128) {
        int n = n0 + tid;
        float rs = 0.0f;
        if (n < N) {
            float c = g_cnt[n];
            if (c > 0.5f) rs = 1.0f / (g_segsum[n] * c);
        }
        sRs[tid] = rs;
    }
    __syncthreads();

    // gather X2 = [agg*rs | nf] transposed
    for (int it = 0; it < 8; ++it) {
        int task = it * 512 + tid;
        int m = task & 127;
        int s = task >> 7;    // 0..31
        int n = n0 + m;
        float4 v = make_float4(0.f, 0.f, 0.f, 0.f);
        if (n < N) {
            if (s < 16) {
                v = *(const float4*)&g_agg[(size_t)n * 64 + s * 4];
                float rs = sRs[m];
                v.x *= rs; v.y *= rs; v.z *= rs; v.w *= rs;
            } else {
                v = *(const float4*)&nf[(size_t)n * 64 + (s - 16) * 4];
            }
        }
        int k0 = s * 4;
        sX[(k0 + 0) * 128 + m] = v.x;
        sX[(k0 + 1) * 128 + m] = v.y;
        sX[(k0 + 2) * 128 + m] = v.z;
        sX[(k0 + 3) * 128 + m] = v.w;
    }
    __syncthreads();

    u64 uacc[2][4];
    #pragma unroll
    for (int p = 0; p < 2; ++p)
        #pragma unroll
        for (int j = 0; j < 4; ++j) uacc[p][j] = 0ull;

    #pragma unroll 1
    for (int chunk = 0; chunk < 2; ++chunk) {
        const int c0 = chunk * 64;
        u64 acc[2][4];
        #pragma unroll
        for (int p = 0; p < 2; ++p)
            #pragma unroll
            for (int j = 0; j < 4; ++j) acc[p][j] = 0ull;

        #pragma unroll 1
        for (int kc = 0; kc < 4; ++kc) {
            __syncthreads();
            {
                int row = tid >> 4;
                int cq  = tid & 15;
                float4 w = *(const float4*)&Wn1[(size_t)(kc * 32 + row) * 128 + c0 + cq * 4];
                *(float4*)&sWd[row * 128 + cq * 8 + 0] = make_float4(w.x, w.x, w.y, w.y);
                *(float4*)&sWd[row * 128 + cq * 8 + 4] = make_float4(w.z, w.z, w.w, w.w);
            }
            __syncthreads();
            const float* xb = &sX[(kc * 32) * 128 + rg * 4];
            const float* wb = &sWd[cg * 8];
            #pragma unroll
            for (int kk = 0; kk < 32; ++kk) {
                ulonglong2 A  = *(const ulonglong2*)(xb + kk * 128);
                ulonglong2 B0 = *(const ulonglong2*)(wb + kk * 128);
                ulonglong2 B1 = *(const ulonglong2*)(wb + kk * 128 + 4);
                FMA2(acc[0][0], A.x, B0.x);
                FMA2(acc[0][1], A.x, B0.y);
                FMA2(acc[0][2], A.x, B1.x);
                FMA2(acc[0][3], A.x, B1.y);
                FMA2(acc[1][0], A.y, B0.x);
                FMA2(acc[1][1], A.y, B0.y);
                FMA2(acc[1][2], A.y, B1.x);
                FMA2(acc[1][3], A.y, B1.y);
            }
        }

        float a[4][4];
        #pragma unroll
        for (int p = 0; p < 2; ++p)
            #pragma unroll
            for (int j = 0; j < 4; ++j)
                UNPK(a[2 * p][j], a[2 * p + 1][j], acc[p][j]);

        float bb0 = bn1[c0 + cg * 4 + 0], bb1 = bn1[c0 + cg * 4 + 1];
        float bb2 = bn1[c0 + cg * 4 + 2], bb3 = bn1[c0 + cg * 4 + 3];
        #pragma unroll
        for (int i = 0; i < 4; ++i) {
            a[i][0] = fmaxf(a[i][0] + bb0, 0.0f);
            a[i][1] = fmaxf(a[i][1] + bb1, 0.0f);
            a[i][2] = fmaxf(a[i][2] + bb2, 0.0f);
            a[i][3] = fmaxf(a[i][3] + bb3, 0.0f);
        }

        #pragma unroll
        for (int j = 0; j < 4; ++j) {
            u64 v0, v1;
            PACK(v0, a[0][j], a[1][j]);
            PACK(v1, a[2][j], a[3][j]);
            *(u64*)&sH[(cg * 4 + j) * 132 + rg * 4]     = v0;
            *(u64*)&sH[(cg * 4 + j) * 132 + rg * 4 + 2] = v1;
        }
        __syncthreads();
        const float* hb  = &sH[rg * 4];
        const float* w2b = &sWn2d[c0 * 128 + cg * 8];
        #pragma unroll
        for (int hh = 0; hh < 64; ++hh) {
            ulonglong2 A  = *(const ulonglong2*)(hb + hh * 132);
            ulonglong2 B0 = *(const ulonglong2*)(w2b + hh * 128);
            ulonglong2 B1 = *(const ulonglong2*)(w2b + hh * 128 + 4);
            FMA2(uacc[0][0], A.x, B0.x);
            FMA2(uacc[0][1], A.x, B0.y);
            FMA2(uacc[0][2], A.x, B1.x);
            FMA2(uacc[0][3], A.x, B1.y);
            FMA2(uacc[1][0], A.y, B0.x);
            FMA2(uacc[1][1], A.y, B0.y);
            FMA2(uacc[1][2], A.y, B1.x);
            FMA2(uacc[1][3], A.y, B1.y);
        }
        __syncthreads();
    }

    float u[4][4];
    #pragma unroll
    for (int p = 0; p < 2; ++p)
        #pragma unroll
        for (int j = 0; j < 4; ++j)
            UNPK(u[2 * p][j], u[2 * p + 1][j], uacc[p][j]);

    float o0 = bn2[cg * 4 + 0], o1 = bn2[cg * 4 + 1];
    float o2 = bn2[cg * 4 + 2], o3 = bn2[cg * 4 + 3];
    #pragma unroll
    for (int i = 0; i < 4; ++i) {
        int n = n0 + rg * 4 + i;
        if (n < N) {
            float4 o = make_float4(u[i][0] + o0, u[i][1] + o1,
                                   u[i][2] + o2, u[i][3] + o3);
            *(float4*)&unf_out[(size_t)n * 64 + cg * 4] = o;
        }
    }
}

// ---------------------------------------------------------------------------
// launch
// ---------------------------------------------------------------------------
extern "C" void kernel_launch(void* const* d_in, const int* in_sizes, int n_in,
                              void* d_out, int out_size)
{
    const float* nf  = (const float*)d_in[0];
    const float* ef  = (const float*)d_in[1];
    const float* We1 = (const float*)d_in[2];
    const float* be1 = (const float*)d_in[3];
    const float* We2 = (const float*)d_in[4];
    const float* be2 = (const float*)d_in[5];
    const float* Wa1 = (const float*)d_in[6];
    const float* ba1 = (const float*)d_in[7];
    const float* Wa2 = (const float*)d_in[8];
    const float* ba2 = (const float*)d_in[9];
    const float* Wn1 = (const float*)d_in[10];
    const float* bn1 = (const float*)d_in[11];
    const float* Wn2 = (const float*)d_in[12];
    const float* bn2 = (const float*)d_in[13];
    const int*   src = (const int*)d_in[14];
    const int*   dst = (const int*)d_in[15];

    const int N = in_sizes[0] / 64;
    const int E = in_sizes[14];

    float* unf_out = (float*)d_out;                       // [N,64] first (ref return order)
    float* uef_out = (float*)d_out + (size_t)N * 64;      // [E,64] second

    cudaFuncSetAttribute(k1_edge, cudaFuncAttributeMaxDynamicSharedMemorySize, EDGE_SMEM_BYTES);
    cudaFuncSetAttribute(k3_node, cudaFuncAttributeMaxDynamicSharedMemorySize, NODE_SMEM_BYTES);

    k0_init<<<(N * 64 + 255) / 256, 256>>>(N);
    k1_edge<<<(E + 127) / 128, 512, EDGE_SMEM_BYTES>>>(
        nf, ef, We1, be1, We2, be2, Wa1, ba1, Wa2, ba2, src, dst, uef_out, E);
    k3_node<<<(N + 127) / 128, 512, NODE_SMEM_BYTES>>>(
        nf, Wn1, bn1, Wn2, bn2, unf_out, N);
}

// round 10
// speedup vs baseline: 2.8404x; 1.5693x over previous
#include <cuda_runtime.h>
#include <cuda_bf16.h>
#include <mma.h>
#include <stdint.h>
#include <math.h>

using namespace nvcuda;

typedef unsigned long long u64;
typedef unsigned int u32;

// ---------------------------------------------------------------------------
// Scratch (static __device__ arrays; no dynamic allocation allowed)
// ---------------------------------------------------------------------------
#define MAX_N 50048

__device__ __align__(16) float g_segsum[MAX_N];
__device__ __align__(16) float g_cnt[MAX_N];
__device__ __align__(16) float g_agg[50000 * 64];

// Pre-split weights (filled by k_prep), plain row-major bf16 hi/lo images.
// W1cat: [192][256]  (cols 0..127 = We1, 128..255 = Wa1)
__device__ __align__(16) __nv_bfloat16 gW1h[192 * 256];
__device__ __align__(16) __nv_bfloat16 gW1l[192 * 256];
// We2: [128][64]
__device__ __align__(16) __nv_bfloat16 gW2h[128 * 64];
__device__ __align__(16) __nv_bfloat16 gW2l[128 * 64];

// fp32 -> bf16 hi/lo split
__device__ __forceinline__ void split2(float v, unsigned short& h, unsigned short& l) {
    __nv_bfloat16 bh = __float2bfloat16_rn(v);
    float r = v - __bfloat162float(bh);
    __nv_bfloat16 bl = __float2bfloat16_rn(r);
    h = __bfloat16_as_ushort(bh);
    l = __bfloat16_as_ushort(bl);
}

__device__ __forceinline__ void red_add_v4(float* p, float4 v) {
    asm volatile("red.global.add.v4.f32 [%0], {%1,%2,%3,%4};"
                 :: "l"(__cvta_generic_to_global(p)),
                    "f"(v.x), "f"(v.y), "f"(v.z), "f"(v.w)
                 : "memory");
}

// ---------------------------------------------------------------------------
// K0: zero-init scratch
// ---------------------------------------------------------------------------
__global__ void k0_init(int N) {
    int i = blockIdx.x * blockDim.x + threadIdx.x;
    if (i < N) {
        g_segsum[i] = 0.0f;
        g_cnt[i]    = 0.0f;
    }
    if (i < N * 64) g_agg[i] = 0.0f;
}

// ---------------------------------------------------------------------------
// K_PREP: bf16 hi/lo split of weights into row-major global images.
// ---------------------------------------------------------------------------
__global__ void k_prep(const float* __restrict__ We1, const float* __restrict__ Wa1,
                       const float* __restrict__ We2) {
    int idx = blockIdx.x * blockDim.x + threadIdx.x;
    if (idx < 49152) {                    // 192*256
        int n = idx & 255, k = idx >> 8;
        float v = (n < 128) ? We1[(size_t)k * 128 + n]
                            : Wa1[(size_t)k * 128 + (n - 128)];
        unsigned short h, l; split2(v, h, l);
        gW1h[idx] = __ushort_as_bfloat16(h);
        gW1l[idx] = __ushort_as_bfloat16(l);
    } else if (idx < 49152 + 8192) {      // 128*64
        int t = idx - 49152;
        float v = We2[t];
        unsigned short h, l; split2(v, h, l);
        gW2h[t] = __ushort_as_bfloat16(h);
        gW2l[t] = __ushort_as_bfloat16(l);
    }
}

// ---------------------------------------------------------------------------
// K1: WMMA (HMMA) edge kernel. 1 CTA = 128 edges, 256 threads (8 warps).
//   GEMM1: X[128x192] @ W1cat[192x256] in 4 N-chunks of 64, bf16 3-term split.
//   He chunk fragments held in registers until X smem is dead, then dumped
//   (bias+ReLU+re-split) into sH overlaying sX.  Attention chunks reduced to
//   logits immediately.  GEMM2: H[128x128] @ We2[128x64].  Epilogue: exp,
//   segment atomics, red.add aggregate (same as proven scalar version).
//
// SMEM byte map (total 195072):
//   [0      ,102400): sXh[128][200] + sXl       -> later sHh[128][136]+sHl
//   [102400 ,157696): sWh[192][72] + sWl        -> later sW2h[128][72]+sW2l
//   [157696 ,194560): sC  f32 [128][72]
//   [194560 ,195072): sLog[128] f32
// ---------------------------------------------------------------------------
#define LDX 200
#define LDW 72
#define LDH 136
#define LDC 72

#define SM_XH   0
#define SM_XL   51200
#define SM_HH   0
#define SM_HL   34816
#define SM_WH   102400
#define SM_WL   130048
#define SM_W2H  102400
#define SM_W2L  120832
#define SM_C    157696
#define SM_LOG  194560
#define K1_SMEM_BYTES 195072

typedef wmma::fragment<wmma::accumulator, 16, 16, 16, float> FragC;
typedef wmma::fragment<wmma::matrix_a, 16, 16, 16, __nv_bfloat16, wmma::row_major> FragA;
typedef wmma::fragment<wmma::matrix_b, 16, 16, 16, __nv_bfloat16, wmma::row_major> FragB;

// C[w][j] += A(h+l) @ B(h+l), 3-term split.  A: [128][lda] tiles row w.
__device__ __forceinline__ void wmma_block(
    FragC (&cc)[4],
    const __nv_bfloat16* sAh, const __nv_bfloat16* sAl, int lda,
    const __nv_bfloat16* sBh, const __nv_bfloat16* sBl, int ldb,
    int ksteps, int w)
{
    #pragma unroll
    for (int j = 0; j < 4; ++j) wmma::fill_fragment(cc[j], 0.0f);
    #pragma unroll 1
    for (int k = 0; k < ksteps; ++k) {
        FragA ah, al;
        wmma::load_matrix_sync(ah, sAh + (size_t)w * 16 * lda + k * 16, lda);
        wmma::load_matrix_sync(al, sAl + (size_t)w * 16 * lda + k * 16, lda);
        #pragma unroll
        for (int j = 0; j < 4; ++j) {
            FragB bh, bl;
            wmma::load_matrix_sync(bh, sBh + (size_t)k * 16 * ldb + j * 16, ldb);
            wmma::load_matrix_sync(bl, sBl + (size_t)k * 16 * ldb + j * 16, ldb);
            wmma::mma_sync(cc[j], ah, bh, cc[j]);
            wmma::mma_sync(cc[j], ah, bl, cc[j]);
            wmma::mma_sync(cc[j], al, bh, cc[j]);
        }
    }
}

__device__ __forceinline__ void store_c(char* smc, FragC (&cc)[4], int w) {
    float* sC = (float*)(smc + SM_C);
    #pragma unroll
    for (int j = 0; j < 4; ++j)
        wmma::store_matrix_sync(sC + (size_t)w * 16 * LDC + j * 16, cc[j], LDC,
                                wmma::mem_row_major);
}

// stage one 64-col chunk of W1cat (h+l) into sW
__device__ __forceinline__ void stage_w1(char* smc, int nc, int tid) {
    const u32* sh = (const u32*)gW1h;
    const u32* sl = (const u32*)gW1l;
    u32* dh = (u32*)(smc + SM_WH);
    u32* dl = (u32*)(smc + SM_WL);
    for (int i = tid; i < 6144; i += 256) {      // 192 rows x 32 u32
        int row = i >> 5, c2 = i & 31;
        dh[row * (LDW / 2) + c2] = sh[row * 128 + nc * 32 + c2];
        dl[row * (LDW / 2) + c2] = sl[row * 128 + nc * 32 + c2];
    }
}

__global__ __launch_bounds__(256, 1)
void k1_edge(const float* __restrict__ nf,  const float* __restrict__ ef,
             const float* __restrict__ be1, const float* __restrict__ be2,
             const float* __restrict__ ba1, const float* __restrict__ ba2,
             const float* __restrict__ Wa2,
             const int* __restrict__ src,   const int* __restrict__ dst,
             float* __restrict__ uef_out, int E)
{
    extern __shared__ char smc[];
    const int tid = threadIdx.x;
    const int w   = tid >> 5;
    const int e0  = blockIdx.x * 128;

    float* sLog = (float*)(smc + SM_LOG);
    if (tid < 128) sLog[tid] = 0.0f;

    // --- gather X [128][192], split -> sXh/sXl ---
    __nv_bfloat16* sXh = (__nv_bfloat16*)(smc + SM_XH);
    __nv_bfloat16* sXl = (__nv_bfloat16*)(smc + SM_XL);
    for (int it = 0; it < 24; ++it) {
        int task = it * 256 + tid;        // 0..6143 = 128 rows x 48 float4
        int m = task & 127;
        int s = task >> 7;                // 0..47
        int e = e0 + m;
        float4 v = make_float4(0.f, 0.f, 0.f, 0.f);
        if (e < E) {
            if (s < 16)      v = *(const float4*)&ef[(size_t)e * 64 + s * 4];
            else if (s < 32) v = *(const float4*)&nf[(size_t)src[e] * 64 + (s - 16) * 4];
            else             v = *(const float4*)&nf[(size_t)dst[e] * 64 + (s - 32) * 4];
        }
        unsigned short h0,l0,h1,l1,h2,l2,h3,l3;
        split2(v.x, h0, l0); split2(v.y, h1, l1);
        split2(v.z, h2, l2); split2(v.w, h3, l3);
        u32* ph = (u32*)(sXh + (size_t)m * LDX + s * 4);
        u32* pl = (u32*)(sXl + (size_t)m * LDX + s * 4);
        ph[0] = (u32)h0 | ((u32)h1 << 16);
        ph[1] = (u32)h2 | ((u32)h3 << 16);
        pl[0] = (u32)l0 | ((u32)l1 << 16);
        pl[1] = (u32)l2 | ((u32)l3 << 16);
    }
    stage_w1(smc, 0, tid);
    __syncthreads();

    __nv_bfloat16* sWh = (__nv_bfloat16*)(smc + SM_WH);
    __nv_bfloat16* sWl = (__nv_bfloat16*)(smc + SM_WL);
    float* sC = (float*)(smc + SM_C);

    FragC cH0[4], cH1[4];

    // --- GEMM1 chunk 0 (We1 cols 0..63), hold frags ---
    wmma_block(cH0, sXh, sXl, LDX, sWh, sWl, LDW, 12, w);
    __syncthreads();
    stage_w1(smc, 1, tid);
    __syncthreads();

    // --- chunk 1 (We1 cols 64..127), hold frags ---
    wmma_block(cH1, sXh, sXl, LDX, sWh, sWl, LDW, 12, w);
    __syncthreads();
    stage_w1(smc, 2, tid);
    __syncthreads();

    // --- chunk 2 (Wa1 cols 0..63): logits partial ---
    {
        FragC cT[4];
        wmma_block(cT, sXh, sXl, LDX, sWh, sWl, LDW, 12, w);
        store_c(smc, cT, w);
        __syncthreads();
        int row = tid & 127, half = tid >> 7;
        float p = 0.0f;
        #pragma unroll
        for (int c = 0; c < 32; ++c) {
            int col = half * 32 + c;
            p += fmaxf(sC[row * LDC + col] + ba1[col], 0.0f) * Wa2[col];
        }
        atomicAdd(&sLog[row], p);
        __syncthreads();
        stage_w1(smc, 3, tid);
        __syncthreads();
    }
    // --- chunk 3 (Wa1 cols 64..127): logits partial ---
    {
        FragC cT[4];
        wmma_block(cT, sXh, sXl, LDX, sWh, sWl, LDW, 12, w);
        store_c(smc, cT, w);
        __syncthreads();
        int row = tid & 127, half = tid >> 7;
        float p = 0.0f;
        #pragma unroll
        for (int c = 0; c < 32; ++c) {
            int col = half * 32 + c;
            p += fmaxf(sC[row * LDC + col] + ba1[64 + col], 0.0f) * Wa2[64 + col];
        }
        atomicAdd(&sLog[row], p);
        __syncthreads();
    }

    // --- dump He chunks: bias + ReLU + re-split into sH (overlays dead sX) ---
    __nv_bfloat16* sHh = (__nv_bfloat16*)(smc + SM_HH);
    __nv_bfloat16* sHl = (__nv_bfloat16*)(smc + SM_HL);
    #pragma unroll 1
    for (int c2 = 0; c2 < 2; ++c2) {
        if (c2 == 0) store_c(smc, cH0, w);
        else         store_c(smc, cH1, w);
        __syncthreads();
        for (int i = tid; i < 8192; i += 256) {
            int row = i >> 6, col = i & 63;
            float v = fmaxf(sC[row * LDC + col] + be1[c2 * 64 + col], 0.0f);
            unsigned short h, l; split2(v, h, l);
            sHh[(size_t)row * LDH + c2 * 64 + col] = __ushort_as_bfloat16(h);
            sHl[(size_t)row * LDH + c2 * 64 + col] = __ushort_as_bfloat16(l);
        }
        __syncthreads();
    }

    // --- stage We2 (h+l) into sW2 region, then GEMM2 ---
    {
        const u32* sh = (const u32*)gW2h;
        const u32* sl = (const u32*)gW2l;
        u32* dh = (u32*)(smc + SM_W2H);
        u32* dl = (u32*)(smc + SM_W2L);
        for (int i = tid; i < 4096; i += 256) {   // 128 rows x 32 u32
            int row = i >> 5, c2 = i & 31;
            dh[row * (LDW / 2) + c2] = sh[row * 32 + c2];
            dl[row * (LDW / 2) + c2] = sl[row * 32 + c2];
        }
    }
    __syncthreads();

    {
        FragC cU[4];
        wmma_block(cU, sHh, sHl, LDH,
                   (__nv_bfloat16*)(smc + SM_W2H), (__nv_bfloat16*)(smc + SM_W2L),
                   LDW, 8, w);
        store_c(smc, cU, w);
    }
    __syncthreads();

    // --- epilogue: logits->exp, atomics, uef write, aggregate ---
    if (tid < 128) {
        int e = e0 + tid;
        if (e < E) {
            float lg = sLog[tid] + ba2[0];
            float ex = __expf(lg);        // no max-subtraction: logits are O(1)
            int d = dst[e];
            atomicAdd(&g_segsum[d], ex);
            atomicAdd(&g_cnt[d], 1.0f);
            float* orow = uef_out + (size_t)e * 64;
            float* arow = g_agg + (size_t)d * 64;
            const float* crow = sC + (size_t)tid * LDC;
            #pragma unroll
            for (int q = 0; q < 16; ++q) {
                float4 c = *(const float4*)(crow + q * 4);
                float4 o = make_float4(c.x + be2[q*4 + 0], c.y + be2[q*4 + 1],
                                       c.z + be2[q*4 + 2], c.w + be2[q*4 + 3]);
                *(float4*)(orow + q * 4) = o;
                float4 vv = make_float4(o.x * ex, o.y * ex, o.z * ex, o.w * ex);
                red_add_v4(arow + q * 4, vv);
            }
        }
    }
}

// ---------------------------------------------------------------------------
// K3: node MLP (proven version: 256 threads, FFMA2+DUP2)
// ---------------------------------------------------------------------------
#define FMA2(d, a, b) asm("fma.rn.f32x2 %0, %1, %2, %0;" : "+l"(d) : "l"(a), "l"(b))
#define DUP2(d, s)    asm("mov.b64 %0, {%1, %1};" : "=l"(d) : "f"(s))
union F4U2 { float4 f; u64 u[2]; };
union U2F  { u64 u; float2 f; };
__device__ __forceinline__ float lane_of(u64 v, int h) {
    U2F t; t.u = v; return h ? t.f.y : t.f.x;
}

#define NODE_SMEM_FLOATS (16384 + 2048 + 8448 + 8192 + 128)
#define NODE_SMEM_BYTES  (NODE_SMEM_FLOATS * 4)

__global__ __launch_bounds__(256, 1)
void k3_node(const float* __restrict__ nf,
             const float* __restrict__ Wn1, const float* __restrict__ bn1,
             const float* __restrict__ Wn2, const float* __restrict__ bn2,
             float* __restrict__ unf_out, int N)
{
    extern __shared__ float sm[];
    float* sX   = sm;            // [128][128]
    float* sW   = sX + 16384;    // [32][64]
    float* sH   = sW + 2048;     // [64][132]
    float* sWn2 = sH + 8448;     // [128][64]
    float* sRs  = sWn2 + 8192;   // [128]

    const int tid = threadIdx.x;
    const int tx  = tid & 15;
    const int ty  = tid >> 4;
    const int n0  = blockIdx.x * 128;

    #pragma unroll
    for (int i = tid; i < 2048; i += 256)
        ((float4*)sWn2)[i] = ((const float4*)Wn2)[i];
    if (tid < 128) {
        int n = n0 + tid;
        float rs = 0.0f;
        if (n < N) {
            float c = g_cnt[n];
            if (c > 0.5f) rs = 1.0f / (g_segsum[n] * c);
        }
        sRs[tid] = rs;
    }
    __syncthreads();

    for (int it = 0; it < 16; ++it) {
        int task = it * 256 + tid;
        if (task >= 4096) break;
        int m = task & 127;
        int s = task >> 7;
        int n = n0 + m;
        float4 v = make_float4(0.f, 0.f, 0.f, 0.f);
        if (n < N) {
            if (s < 16) {
                v = *(const float4*)&g_agg[(size_t)n * 64 + s * 4];
                float rs = sRs[m];
                v.x *= rs; v.y *= rs; v.z *= rs; v.w *= rs;
            } else {
                v = *(const float4*)&nf[(size_t)n * 64 + (s - 16) * 4];
            }
        }
        int k0 = s * 4;
        sX[(k0 + 0) * 128 + m] = v.x;
        sX[(k0 + 1) * 128 + m] = v.y;
        sX[(k0 + 2) * 128 + m] = v.z;
        sX[(k0 + 3) * 128 + m] = v.w;
    }
    __syncthreads();

    u64 uacc2[8][2];
    #pragma unroll
    for (int i = 0; i < 8; ++i) { uacc2[i][0] = 0ull; uacc2[i][1] = 0ull; }

    #pragma unroll 1
    for (int chunk = 0; chunk < 2; ++chunk) {
        const int c0 = chunk * 64;
        u64 acc2[8][2];
        #pragma unroll
        for (int i = 0; i < 8; ++i) { acc2[i][0] = 0ull; acc2[i][1] = 0ull; }

        #pragma unroll 1
        for (int kc = 0; kc < 4; ++kc) {
            __syncthreads();
            #pragma unroll
            for (int i = tid; i < 512; i += 256) {
                int row = i >> 4;
                int cq  = i & 15;
                *(float4*)&sW[row * 64 + cq * 4] =
                    *(const float4*)&Wn1[(size_t)(kc * 32 + row) * 128 + c0 + cq * 4];
            }
            __syncthreads();
            #pragma unroll
            for (int kk = 0; kk < 32; ++kk) {
                const float* xr = &sX[(kc * 32 + kk) * 128 + ty * 8];
                float4 a0 = *(const float4*)xr;
                float4 a1 = *(const float4*)(xr + 4);
                F4U2 B; B.f = *(const float4*)&sW[kk * 64 + tx * 4];
                u64 ad[8];
                DUP2(ad[0], a0.x); DUP2(ad[1], a0.y); DUP2(ad[2], a0.z); DUP2(ad[3], a0.w);
                DUP2(ad[4], a1.x); DUP2(ad[5], a1.y); DUP2(ad[6], a1.z); DUP2(ad[7], a1.w);
                #pragma unroll
                for (int i = 0; i < 8; ++i) {
                    FMA2(acc2[i][0], ad[i], B.u[0]);
                    FMA2(acc2[i][1], ad[i], B.u[1]);
                }
            }
        }

        float acc[8][4];
        #pragma unroll
        for (int i = 0; i < 8; ++i) {
            U2F p0, p1; p0.u = acc2[i][0]; p1.u = acc2[i][1];
            acc[i][0] = p0.f.x; acc[i][1] = p0.f.y;
            acc[i][2] = p1.f.x; acc[i][3] = p1.f.y;
        }
        float bj0 = bn1[c0 + tx * 4 + 0], bj1 = bn1[c0 + tx * 4 + 1];
        float bj2 = bn1[c0 + tx * 4 + 2], bj3 = bn1[c0 + tx * 4 + 3];
        #pragma unroll
        for (int i = 0; i < 8; ++i) {
            acc[i][0] = fmaxf(acc[i][0] + bj0, 0.0f);
            acc[i][1] = fmaxf(acc[i][1] + bj1, 0.0f);
            acc[i][2] = fmaxf(acc[i][2] + bj2, 0.0f);
            acc[i][3] = fmaxf(acc[i][3] + bj3, 0.0f);
        }

        #pragma unroll
        for (int i = 0; i < 8; ++i) {
            sH[(tx * 4 + 0) * 132 + ty * 8 + i] = acc[i][0];
            sH[(tx * 4 + 1) * 132 + ty * 8 + i] = acc[i][1];
            sH[(tx * 4 + 2) * 132 + ty * 8 + i] = acc[i][2];
            sH[(tx * 4 + 3) * 132 + ty * 8 + i] = acc[i][3];
        }
        __syncthreads();
        #pragma unroll
        for (int hh = 0; hh < 64; ++hh) {
            const float* hr = &sH[hh * 132 + ty * 8];
            float4 a0 = *(const float4*)hr;
            float4 a1 = *(const float4*)(hr + 4);
            F4U2 B; B.f = *(const float4*)&sWn2[(c0 + hh) * 64 + tx * 4];
            u64 ad[8];
            DUP2(ad[0], a0.x); DUP2(ad[1], a0.y); DUP2(ad[2], a0.z); DUP2(ad[3], a0.w);
            DUP2(ad[4], a1.x); DUP2(ad[5], a1.y); DUP2(ad[6], a1.z); DUP2(ad[7], a1.w);
            #pragma unroll
            for (int i = 0; i < 8; ++i) {
                FMA2(uacc2[i][0], ad[i], B.u[0]);
                FMA2(uacc2[i][1], ad[i], B.u[1]);
            }
        }
        __syncthreads();
    }

    float o0 = bn2[tx * 4 + 0], o1 = bn2[tx * 4 + 1];
    float o2 = bn2[tx * 4 + 2], o3 = bn2[tx * 4 + 3];
    #pragma unroll
    for (int i = 0; i < 8; ++i) {
        int n = n0 + ty * 8 + i;
        if (n < N) {
            float4 o = make_float4(lane_of(uacc2[i][0], 0) + o0,
                                   lane_of(uacc2[i][0], 1) + o1,
                                   lane_of(uacc2[i][1], 0) + o2,
                                   lane_of(uacc2[i][1], 1) + o3);
            *(float4*)&unf_out[(size_t)n * 64 + tx * 4] = o;
        }
    }
}

// ---------------------------------------------------------------------------
// launch
// ---------------------------------------------------------------------------
extern "C" void kernel_launch(void* const* d_in, const int* in_sizes, int n_in,
                              void* d_out, int out_size)
{
    const float* nf  = (const float*)d_in[0];
    const float* ef  = (const float*)d_in[1];
    const float* We1 = (const float*)d_in[2];
    const float* be1 = (const float*)d_in[3];
    const float* We2 = (const float*)d_in[4];
    const float* be2 = (const float*)d_in[5];
    const float* Wa1 = (const float*)d_in[6];
    const float* ba1 = (const float*)d_in[7];
    const float* Wa2 = (const float*)d_in[8];
    const float* ba2 = (const float*)d_in[9];
    const float* Wn1 = (const float*)d_in[10];
    const float* bn1 = (const float*)d_in[11];
    const float* Wn2 = (const float*)d_in[12];
    const float* bn2 = (const float*)d_in[13];
    const int*   src = (const int*)d_in[14];
    const int*   dst = (const int*)d_in[15];

    const int N = in_sizes[0] / 64;
    const int E = in_sizes[14];

    float* unf_out = (float*)d_out;                       // [N,64] first (ref return order)
    float* uef_out = (float*)d_out + (size_t)N * 64;      // [E,64] second

    cudaFuncSetAttribute(k1_edge, cudaFuncAttributeMaxDynamicSharedMemorySize, K1_SMEM_BYTES);
    cudaFuncSetAttribute(k3_node, cudaFuncAttributeMaxDynamicSharedMemorySize, NODE_SMEM_BYTES);

    k0_init<<<(N * 64 + 255) / 256, 256>>>(N);
    k_prep<<<224, 256>>>(We1, Wa1, We2);
    k1_edge<<<(E + 127) / 128, 256, K1_SMEM_BYTES>>>(
        nf, ef, be1, be2, ba1, ba2, Wa2, src, dst, uef_out, E);
    k3_node<<<(N + 127) / 128, 256, NODE_SMEM_BYTES>>>(
        nf, Wn1, bn1, Wn2, bn2, unf_out, N);
}

// round 11
// speedup vs baseline: 3.3464x; 1.1781x over previous
#include <cuda_runtime.h>
#include <cuda_bf16.h>
#include <mma.h>
#include <stdint.h>
#include <math.h>

using namespace nvcuda;

typedef unsigned long long u64;
typedef unsigned int u32;

// ---------------------------------------------------------------------------
// Scratch (static __device__ arrays; no dynamic allocation allowed)
// ---------------------------------------------------------------------------
#define MAX_N 50048

__device__ __align__(16) float g_segsum[MAX_N];
__device__ __align__(16) float g_cnt[MAX_N];
__device__ __align__(16) float g_agg[50000 * 64];

// Pre-split weights (filled by k_prep), row-major bf16 hi/lo images.
// W1cat: [192][256]  (cols 0..127 = We1, 128..255 = Wa1)
__device__ __align__(16) __nv_bfloat16 gW1h[192 * 256];
__device__ __align__(16) __nv_bfloat16 gW1l[192 * 256];
// We2: [128][64]
__device__ __align__(16) __nv_bfloat16 gW2h[128 * 64];
__device__ __align__(16) __nv_bfloat16 gW2l[128 * 64];

// fp32 -> bf16 hi/lo split
__device__ __forceinline__ void split2(float v, unsigned short& h, unsigned short& l) {
    __nv_bfloat16 bh = __float2bfloat16_rn(v);
    float r = v - __bfloat162float(bh);
    __nv_bfloat16 bl = __float2bfloat16_rn(r);
    h = __bfloat16_as_ushort(bh);
    l = __bfloat16_as_ushort(bl);
}

__device__ __forceinline__ void red_add_v4(float* p, float4 v) {
    asm volatile("red.global.add.v4.f32 [%0], {%1,%2,%3,%4};"
                 :: "l"(__cvta_generic_to_global(p)),
                    "f"(v.x), "f"(v.y), "f"(v.z), "f"(v.w)
                 : "memory");
}

// ---------------------------------------------------------------------------
// K0: zero-init scratch
// ---------------------------------------------------------------------------
__global__ void k0_init(int N) {
    int i = blockIdx.x * blockDim.x + threadIdx.x;
    if (i < N) {
        g_segsum[i] = 0.0f;
        g_cnt[i]    = 0.0f;
    }
    if (i < N * 64) g_agg[i] = 0.0f;
}

// ---------------------------------------------------------------------------
// K_PREP: bf16 hi/lo split of weights into row-major global images.
// ---------------------------------------------------------------------------
__global__ void k_prep(const float* __restrict__ We1, const float* __restrict__ Wa1,
                       const float* __restrict__ We2) {
    int idx = blockIdx.x * blockDim.x + threadIdx.x;
    if (idx < 49152) {                    // 192*256
        int n = idx & 255, k = idx >> 8;
        float v = (n < 128) ? We1[(size_t)k * 128 + n]
                            : Wa1[(size_t)k * 128 + (n - 128)];
        unsigned short h, l; split2(v, h, l);
        gW1h[idx] = __ushort_as_bfloat16(h);
        gW1l[idx] = __ushort_as_bfloat16(l);
    } else if (idx < 49152 + 8192) {      // 128*64
        int t = idx - 49152;
        float v = We2[t];
        unsigned short h, l; split2(v, h, l);
        gW2h[t] = __ushort_as_bfloat16(h);
        gW2l[t] = __ushort_as_bfloat16(l);
    }
}

// ---------------------------------------------------------------------------
// K1: WMMA edge kernel, 512 threads / 16 warps, full-width weight staging.
//   Warp (wr = w>>1, wc = w&1): rows wr*16..+15, cols wc*64..+63.
//   GEMM1 in 2 phases: He (We1 full, frags held), attn (Wa1 full -> logits).
//   3-term bf16 split everywhere (D = Ah*Bh + Ah*Bl + Al*Bh).
//
// SMEM byte map (total 209408):
//   [0      ,102400): sXh[128][200] + sXl    -> later sHh[128][136]+sHl
//   [102400 ,206848): sW1h[192][136] + sW1l  -> later sC f32[128][136]
//   [172032 ,208896): sW2h[128][72] + sW2l   (staged after attn phase)
//   [208896 ,209408): sLog[128] f32
// ---------------------------------------------------------------------------
#define LDX  200
#define LDW  136
#define LDH  136
#define LDC  136
#define LDW2 72

#define SM_XH   0
#define SM_XL   51200
#define SM_HH   0
#define SM_HL   34816
#define SM_W1H  102400
#define SM_W1L  154624
#define SM_C    102400
#define SM_W2H  172032
#define SM_W2L  190464
#define SM_LOG  208896
#define K1_SMEM_BYTES 209408

typedef wmma::fragment<wmma::accumulator, 16, 16, 16, float> FragC;
typedef wmma::fragment<wmma::matrix_a, 16, 16, 16, __nv_bfloat16, wmma::row_major> FragA;
typedef wmma::fragment<wmma::matrix_b, 16, 16, 16, __nv_bfloat16, wmma::row_major> FragB;

// cc[0..3] = A(h+l) @ B(h+l) over 4 j-tiles at colbase, 3-term split.
__device__ __forceinline__ void wmma_block4(
    FragC (&cc)[4],
    const __nv_bfloat16* sAh, const __nv_bfloat16* sAl, int lda,
    const __nv_bfloat16* sBh, const __nv_bfloat16* sBl, int ldb,
    int ksteps, int wr, int colbase)
{
    #pragma unroll
    for (int j = 0; j < 4; ++j) wmma::fill_fragment(cc[j], 0.0f);
    #pragma unroll 1
    for (int k = 0; k < ksteps; ++k) {
        FragA ah, al;
        wmma::load_matrix_sync(ah, sAh + (size_t)wr * 16 * lda + k * 16, lda);
        wmma::load_matrix_sync(al, sAl + (size_t)wr * 16 * lda + k * 16, lda);
        #pragma unroll
        for (int j = 0; j < 4; ++j) {
            FragB bh, bl;
            wmma::load_matrix_sync(bh, sBh + (size_t)k * 16 * ldb + colbase + j * 16, ldb);
            wmma::load_matrix_sync(bl, sBl + (size_t)k * 16 * ldb + colbase + j * 16, ldb);
            wmma::mma_sync(cc[j], ah, bh, cc[j]);
            wmma::mma_sync(cc[j], ah, bl, cc[j]);
            wmma::mma_sync(cc[j], al, bh, cc[j]);
        }
    }
}

// 2-j-tile variant for GEMM2
__device__ __forceinline__ void wmma_block2(
    FragC (&cc)[2],
    const __nv_bfloat16* sAh, const __nv_bfloat16* sAl, int lda,
    const __nv_bfloat16* sBh, const __nv_bfloat16* sBl, int ldb,
    int ksteps, int wr, int colbase)
{
    #pragma unroll
    for (int j = 0; j < 2; ++j) wmma::fill_fragment(cc[j], 0.0f);
    #pragma unroll 1
    for (int k = 0; k < ksteps; ++k) {
        FragA ah, al;
        wmma::load_matrix_sync(ah, sAh + (size_t)wr * 16 * lda + k * 16, lda);
        wmma::load_matrix_sync(al, sAl + (size_t)wr * 16 * lda + k * 16, lda);
        #pragma unroll
        for (int j = 0; j < 2; ++j) {
            FragB bh, bl;
            wmma::load_matrix_sync(bh, sBh + (size_t)k * 16 * ldb + colbase + j * 16, ldb);
            wmma::load_matrix_sync(bl, sBl + (size_t)k * 16 * ldb + colbase + j * 16, ldb);
            wmma::mma_sync(cc[j], ah, bh, cc[j]);
            wmma::mma_sync(cc[j], ah, bl, cc[j]);
            wmma::mma_sync(cc[j], al, bh, cc[j]);
        }
    }
}

// stage full 128-col block of W1cat (col0_u32=0: We1, 64: Wa1), h+l
__device__ __forceinline__ void stage_w1_full(char* smc, int col0_u32, int tid) {
    const u32* sh = (const u32*)gW1h;
    const u32* sl = (const u32*)gW1l;
    u32* dh = (u32*)(smc + SM_W1H);
    u32* dl = (u32*)(smc + SM_W1L);
    for (int i = tid; i < 12288; i += 512) {     // 192 rows x 64 u32
        int row = i >> 6, c2 = i & 63;
        dh[row * (LDW / 2) + c2] = sh[row * 128 + col0_u32 + c2];
        dl[row * (LDW / 2) + c2] = sl[row * 128 + col0_u32 + c2];
    }
}

__global__ __launch_bounds__(512, 1)
void k1_edge(const float* __restrict__ nf,  const float* __restrict__ ef,
             const float* __restrict__ be1, const float* __restrict__ be2,
             const float* __restrict__ ba1, const float* __restrict__ ba2,
             const float* __restrict__ Wa2,
             const int* __restrict__ src,   const int* __restrict__ dst,
             float* __restrict__ uef_out, int E)
{
    extern __shared__ char smc[];
    const int tid = threadIdx.x;
    const int w   = tid >> 5;
    const int wr  = w >> 1;          // row tile 0..7
    const int wc  = w & 1;           // col half 0..1
    const int e0  = blockIdx.x * 128;

    float* sLog = (float*)(smc + SM_LOG);
    if (tid < 128) sLog[tid] = 0.0f;

    // --- gather X [128][192], split -> sXh/sXl ---
    __nv_bfloat16* sXh = (__nv_bfloat16*)(smc + SM_XH);
    __nv_bfloat16* sXl = (__nv_bfloat16*)(smc + SM_XL);
    for (int it = 0; it < 12; ++it) {
        int task = it * 512 + tid;        // 0..6143 = 128 rows x 48 float4
        int m = task & 127;
        int s = task >> 7;                // 0..47
        int e = e0 + m;
        float4 v = make_float4(0.f, 0.f, 0.f, 0.f);
        if (e < E) {
            if (s < 16)      v = *(const float4*)&ef[(size_t)e * 64 + s * 4];
            else if (s < 32) v = *(const float4*)&nf[(size_t)src[e] * 64 + (s - 16) * 4];
            else             v = *(const float4*)&nf[(size_t)dst[e] * 64 + (s - 32) * 4];
        }
        unsigned short h0,l0,h1,l1,h2,l2,h3,l3;
        split2(v.x, h0, l0); split2(v.y, h1, l1);
        split2(v.z, h2, l2); split2(v.w, h3, l3);
        u32* ph = (u32*)(sXh + (size_t)m * LDX + s * 4);
        u32* pl = (u32*)(sXl + (size_t)m * LDX + s * 4);
        ph[0] = (u32)h0 | ((u32)h1 << 16);
        ph[1] = (u32)h2 | ((u32)h3 << 16);
        pl[0] = (u32)l0 | ((u32)l1 << 16);
        pl[1] = (u32)l2 | ((u32)l3 << 16);
    }
    stage_w1_full(smc, 0, tid);           // We1 full
    __syncthreads();

    __nv_bfloat16* sW1h = (__nv_bfloat16*)(smc + SM_W1H);
    __nv_bfloat16* sW1l = (__nv_bfloat16*)(smc + SM_W1L);
    float* sC = (float*)(smc + SM_C);

    // --- He phase: full 128 cols at once, frags held ---
    FragC cH[4];
    wmma_block4(cH, sXh, sXl, LDX, sW1h, sW1l, LDW, 12, wr, wc * 64);
    __syncthreads();                      // all warps done reading We1

    stage_w1_full(smc, 64, tid);          // Wa1 full
    __syncthreads();

    // --- attention phase ---
    {
        FragC cT[4];
        wmma_block4(cT, sXh, sXl, LDX, sW1h, sW1l, LDW, 12, wr, wc * 64);
        __syncthreads();                  // all warps done reading Wa1 (and X)
        #pragma unroll
        for (int j = 0; j < 4; ++j)
            wmma::store_matrix_sync(sC + (size_t)wr * 16 * LDC + wc * 64 + j * 16,
                                    cT[j], LDC, wmma::mem_row_major);
    }
    __syncthreads();

    // --- logits reduce (4 threads per row) + stage We2 ---
    {
        int row = tid & 127, q = tid >> 7;
        float p = 0.0f;
        #pragma unroll
        for (int c = 0; c < 32; ++c) {
            int col = q * 32 + c;
            p += fmaxf(sC[row * LDC + col] + ba1[col], 0.0f) * Wa2[col];
        }
        atomicAdd(&sLog[row], p);

        const u32* sh = (const u32*)gW2h;
        const u32* sl = (const u32*)gW2l;
        u32* dh = (u32*)(smc + SM_W2H);
        u32* dl = (u32*)(smc + SM_W2L);
        for (int i = tid; i < 4096; i += 512) {   // 128 rows x 32 u32
            int r2 = i >> 5, c2 = i & 31;
            dh[r2 * (LDW2 / 2) + c2] = sh[r2 * 32 + c2];
            dl[r2 * (LDW2 / 2) + c2] = sl[r2 * 32 + c2];
        }
    }
    __syncthreads();

    // --- dump He: store frags -> sC, then bias+ReLU+re-split -> sH ---
    #pragma unroll
    for (int j = 0; j < 4; ++j)
        wmma::store_matrix_sync(sC + (size_t)wr * 16 * LDC + wc * 64 + j * 16,
                                cH[j], LDC, wmma::mem_row_major);
    __syncthreads();

    __nv_bfloat16* sHh = (__nv_bfloat16*)(smc + SM_HH);
    __nv_bfloat16* sHl = (__nv_bfloat16*)(smc + SM_HL);
    for (int i = tid; i < 16384; i += 512) {
        int row = i >> 7, col = i & 127;
        float v = fmaxf(sC[row * LDC + col] + be1[col], 0.0f);
        unsigned short h, l; split2(v, h, l);
        sHh[(size_t)row * LDH + col] = __ushort_as_bfloat16(h);
        sHl[(size_t)row * LDH + col] = __ushort_as_bfloat16(l);
    }
    __syncthreads();

    // --- GEMM2: uef = H @ We2 (each warp 2 j-tiles of its 32 cols) ---
    {
        FragC cU[2];
        wmma_block2(cU, sHh, sHl, LDH,
                    (__nv_bfloat16*)(smc + SM_W2H), (__nv_bfloat16*)(smc + SM_W2L),
                    LDW2, 8, wr, wc * 32);
        #pragma unroll
        for (int j = 0; j < 2; ++j)
            wmma::store_matrix_sync(sC + (size_t)wr * 16 * LDC + wc * 32 + j * 16,
                                    cU[j], LDC, wmma::mem_row_major);
    }
    __syncthreads();

    // --- epilogue: logits->exp, atomics, uef write, aggregate ---
    if (tid < 128) {
        int e = e0 + tid;
        if (e < E) {
            float lg = sLog[tid] + ba2[0];
            float ex = __expf(lg);        // no max-subtraction: logits are O(1)
            int d = dst[e];
            atomicAdd(&g_segsum[d], ex);
            atomicAdd(&g_cnt[d], 1.0f);
            float* orow = uef_out + (size_t)e * 64;
            float* arow = g_agg + (size_t)d * 64;
            const float* crow = sC + (size_t)tid * LDC;
            #pragma unroll
            for (int q = 0; q < 16; ++q) {
                float4 c = *(const float4*)(crow + q * 4);
                float4 o = make_float4(c.x + be2[q*4 + 0], c.y + be2[q*4 + 1],
                                       c.z + be2[q*4 + 2], c.w + be2[q*4 + 3]);
                *(float4*)(orow + q * 4) = o;
                float4 vv = make_float4(o.x * ex, o.y * ex, o.z * ex, o.w * ex);
                red_add_v4(arow + q * 4, vv);
            }
        }
    }
}

// ---------------------------------------------------------------------------
// K3: node MLP (proven version: 256 threads, FFMA2+DUP2)
// ---------------------------------------------------------------------------
#define FMA2(d, a, b) asm("fma.rn.f32x2 %0, %1, %2, %0;" : "+l"(d) : "l"(a), "l"(b))
#define DUP2(d, s)    asm("mov.b64 %0, {%1, %1};" : "=l"(d) : "f"(s))
union F4U2 { float4 f; u64 u[2]; };
union U2F  { u64 u; float2 f; };
__device__ __forceinline__ float lane_of(u64 v, int h) {
    U2F t; t.u = v; return h ? t.f.y : t.f.x;
}

#define NODE_SMEM_FLOATS (16384 + 2048 + 8448 + 8192 + 128)
#define NODE_SMEM_BYTES  (NODE_SMEM_FLOATS * 4)

__global__ __launch_bounds__(256, 1)
void k3_node(const float* __restrict__ nf,
             const float* __restrict__ Wn1, const float* __restrict__ bn1,
             const float* __restrict__ Wn2, const float* __restrict__ bn2,
             float* __restrict__ unf_out, int N)
{
    extern __shared__ float sm[];
    float* sX   = sm;            // [128][128]
    float* sW   = sX + 16384;    // [32][64]
    float* sH   = sW + 2048;     // [64][132]
    float* sWn2 = sH + 8448;     // [128][64]
    float* sRs  = sWn2 + 8192;   // [128]

    const int tid = threadIdx.x;
    const int tx  = tid & 15;
    const int ty  = tid >> 4;
    const int n0  = blockIdx.x * 128;

    #pragma unroll
    for (int i = tid; i < 2048; i += 256)
        ((float4*)sWn2)[i] = ((const float4*)Wn2)[i];
    if (tid < 128) {
        int n = n0 + tid;
        float rs = 0.0f;
        if (n < N) {
            float c = g_cnt[n];
            if (c > 0.5f) rs = 1.0f / (g_segsum[n] * c);
        }
        sRs[tid] = rs;
    }
    __syncthreads();

    for (int it = 0; it < 16; ++it) {
        int task = it * 256 + tid;
        if (task >= 4096) break;
        int m = task & 127;
        int s = task >> 7;
        int n = n0 + m;
        float4 v = make_float4(0.f, 0.f, 0.f, 0.f);
        if (n < N) {
            if (s < 16) {
                v = *(const float4*)&g_agg[(size_t)n * 64 + s * 4];
                float rs = sRs[m];
                v.x *= rs; v.y *= rs; v.z *= rs; v.w *= rs;
            } else {
                v = *(const float4*)&nf[(size_t)n * 64 + (s - 16) * 4];
            }
        }
        int k0 = s * 4;
        sX[(k0 + 0) * 128 + m] = v.x;
        sX[(k0 + 1) * 128 + m] = v.y;
        sX[(k0 + 2) * 128 + m] = v.z;
        sX[(k0 + 3) * 128 + m] = v.w;
    }
    __syncthreads();

    u64 uacc2[8][2];
    #pragma unroll
    for (int i = 0; i < 8; ++i) { uacc2[i][0] = 0ull; uacc2[i][1] = 0ull; }

    #pragma unroll 1
    for (int chunk = 0; chunk < 2; ++chunk) {
        const int c0 = chunk * 64;
        u64 acc2[8][2];
        #pragma unroll
        for (int i = 0; i < 8; ++i) { acc2[i][0] = 0ull; acc2[i][1] = 0ull; }

        #pragma unroll 1
        for (int kc = 0; kc < 4; ++kc) {
            __syncthreads();
            #pragma unroll
            for (int i = tid; i < 512; i += 256) {
                int row = i >> 4;
                int cq  = i & 15;
                *(float4*)&sW[row * 64 + cq * 4] =
                    *(const float4*)&Wn1[(size_t)(kc * 32 + row) * 128 + c0 + cq * 4];
            }
            __syncthreads();
            #pragma unroll
            for (int kk = 0; kk < 32; ++kk) {
                const float* xr = &sX[(kc * 32 + kk) * 128 + ty * 8];
                float4 a0 = *(const float4*)xr;
                float4 a1 = *(const float4*)(xr + 4);
                F4U2 B; B.f = *(const float4*)&sW[kk * 64 + tx * 4];
                u64 ad[8];
                DUP2(ad[0], a0.x); DUP2(ad[1], a0.y); DUP2(ad[2], a0.z); DUP2(ad[3], a0.w);
                DUP2(ad[4], a1.x); DUP2(ad[5], a1.y); DUP2(ad[6], a1.z); DUP2(ad[7], a1.w);
                #pragma unroll
                for (int i = 0; i < 8; ++i) {
                    FMA2(acc2[i][0], ad[i], B.u[0]);
                    FMA2(acc2[i][1], ad[i], B.u[1]);
                }
            }
        }

        float acc[8][4];
        #pragma unroll
        for (int i = 0; i < 8; ++i) {
            U2F p0, p1; p0.u = acc2[i][0]; p1.u = acc2[i][1];
            acc[i][0] = p0.f.x; acc[i][1] = p0.f.y;
            acc[i][2] = p1.f.x; acc[i][3] = p1.f.y;
        }
        float bj0 = bn1[c0 + tx * 4 + 0], bj1 = bn1[c0 + tx * 4 + 1];
        float bj2 = bn1[c0 + tx * 4 + 2], bj3 = bn1[c0 + tx * 4 + 3];
        #pragma unroll
        for (int i = 0; i < 8; ++i) {
            acc[i][0] = fmaxf(acc[i][0] + bj0, 0.0f);
            acc[i][1] = fmaxf(acc[i][1] + bj1, 0.0f);
            acc[i][2] = fmaxf(acc[i][2] + bj2, 0.0f);
            acc[i][3] = fmaxf(acc[i][3] + bj3, 0.0f);
        }

        #pragma unroll
        for (int i = 0; i < 8; ++i) {
            sH[(tx * 4 + 0) * 132 + ty * 8 + i] = acc[i][0];
            sH[(tx * 4 + 1) * 132 + ty * 8 + i] = acc[i][1];
            sH[(tx * 4 + 2) * 132 + ty * 8 + i] = acc[i][2];
            sH[(tx * 4 + 3) * 132 + ty * 8 + i] = acc[i][3];
        }
        __syncthreads();
        #pragma unroll
        for (int hh = 0; hh < 64; ++hh) {
            const float* hr = &sH[hh * 132 + ty * 8];
            float4 a0 = *(const float4*)hr;
            float4 a1 = *(const float4*)(hr + 4);
            F4U2 B; B.f = *(const float4*)&sWn2[(c0 + hh) * 64 + tx * 4];
            u64 ad[8];
            DUP2(ad[0], a0.x); DUP2(ad[1], a0.y); DUP2(ad[2], a0.z); DUP2(ad[3], a0.w);
            DUP2(ad[4], a1.x); DUP2(ad[5], a1.y); DUP2(ad[6], a1.z); DUP2(ad[7], a1.w);
            #pragma unroll
            for (int i = 0; i < 8; ++i) {
                FMA2(uacc2[i][0], ad[i], B.u[0]);
                FMA2(uacc2[i][1], ad[i], B.u[1]);
            }
        }
        __syncthreads();
    }

    float o0 = bn2[tx * 4 + 0], o1 = bn2[tx * 4 + 1];
    float o2 = bn2[tx * 4 + 2], o3 = bn2[tx * 4 + 3];
    #pragma unroll
    for (int i = 0; i < 8; ++i) {
        int n = n0 + ty * 8 + i;
        if (n < N) {
            float4 o = make_float4(lane_of(uacc2[i][0], 0) + o0,
                                   lane_of(uacc2[i][0], 1) + o1,
                                   lane_of(uacc2[i][1], 0) + o2,
                                   lane_of(uacc2[i][1], 1) + o3);
            *(float4*)&unf_out[(size_t)n * 64 + tx * 4] = o;
        }
    }
}

// ---------------------------------------------------------------------------
// launch
// ---------------------------------------------------------------------------
extern "C" void kernel_launch(void* const* d_in, const int* in_sizes, int n_in,
                              void* d_out, int out_size)
{
    const float* nf  = (const float*)d_in[0];
    const float* ef  = (const float*)d_in[1];
    const float* We1 = (const float*)d_in[2];
    const float* be1 = (const float*)d_in[3];
    const float* We2 = (const float*)d_in[4];
    const float* be2 = (const float*)d_in[5];
    const float* Wa1 = (const float*)d_in[6];
    const float* ba1 = (const float*)d_in[7];
    const float* Wa2 = (const float*)d_in[8];
    const float* ba2 = (const float*)d_in[9];
    const float* Wn1 = (const float*)d_in[10];
    const float* bn1 = (const float*)d_in[11];
    const float* Wn2 = (const float*)d_in[12];
    const float* bn2 = (const float*)d_in[13];
    const int*   src = (const int*)d_in[14];
    const int*   dst = (const int*)d_in[15];

    const int N = in_sizes[0] / 64;
    const int E = in_sizes[14];

    float* unf_out = (float*)d_out;                       // [N,64] first (ref return order)
    float* uef_out = (float*)d_out + (size_t)N * 64;      // [E,64] second

    cudaFuncSetAttribute(k1_edge, cudaFuncAttributeMaxDynamicSharedMemorySize, K1_SMEM_BYTES);
    cudaFuncSetAttribute(k3_node, cudaFuncAttributeMaxDynamicSharedMemorySize, NODE_SMEM_BYTES);

    k0_init<<<(N * 64 + 255) / 256, 256>>>(N);
    k_prep<<<224, 256>>>(We1, Wa1, We2);
    k1_edge<<<(E + 127) / 128, 512, K1_SMEM_BYTES>>>(
        nf, ef, be1, be2, ba1, ba2, Wa2, src, dst, uef_out, E);
    k3_node<<<(N + 127) / 128, 256, NODE_SMEM_BYTES>>>(
        nf, Wn1, bn1, Wn2, bn2, unf_out, N);
}